// round 2
// baseline (speedup 1.0000x reference)
#include <cuda_runtime.h>
#include <cuda_bf16.h>
#include <math.h>

// Problem constants
constexpr int T = 16384;   // tokens
constexpr int H = 2048;    // hidden
constexpr int E = 128;     // experts
constexpr int TOPK = 8;

// GEMM tiling
constexpr int BM = 128;
constexpr int BN = 128;
constexpr int BK = 16;
constexpr int TM = 8;
constexpr int TN = 8;

// C[t][e] = sum_k X[t][k] * W[e][k]    (W is [E,H] nn.Linear layout)
__global__ __launch_bounds__(256) void router_gemm(const float* __restrict__ X,
                                                   const float* __restrict__ W,
                                                   float* __restrict__ C) {
    __shared__ float Xs[2][BK][BM + 4];
    __shared__ float Ws[2][BK][BN + 4];

    const int tid = threadIdx.x;
    const int tx = tid & 15;        // expert-tile coord
    const int ty = tid >> 4;        // token-tile coord
    const int m0 = blockIdx.x * BM;

    // global-load mapping: 256 threads, each loads 2 float4s per tile per operand
    const int lrow = tid >> 2;               // 0..63
    const int lcol = (tid & 3) << 2;         // 0,4,8,12

    const float* Xptr = X + (size_t)(m0 + lrow) * H + lcol;
    const float* Wptr = W + (size_t)lrow * H + lcol;

    float acc[TM][TN];
#pragma unroll
    for (int i = 0; i < TM; i++)
#pragma unroll
        for (int j = 0; j < TN; j++) acc[i][j] = 0.0f;

    float4 xr[2], wr[2];

    // prologue: load k-tile 0
    xr[0] = *reinterpret_cast<const float4*>(Xptr);
    xr[1] = *reinterpret_cast<const float4*>(Xptr + (size_t)64 * H);
    wr[0] = *reinterpret_cast<const float4*>(Wptr);
    wr[1] = *reinterpret_cast<const float4*>(Wptr + (size_t)64 * H);

    // store tile 0 into buffer 0 (transposed: [k][m])
#pragma unroll
    for (int h = 0; h < 2; h++) {
        Xs[0][lcol + 0][lrow + 64 * h] = h ? xr[1].x : xr[0].x;
        Xs[0][lcol + 1][lrow + 64 * h] = h ? xr[1].y : xr[0].y;
        Xs[0][lcol + 2][lrow + 64 * h] = h ? xr[1].z : xr[0].z;
        Xs[0][lcol + 3][lrow + 64 * h] = h ? xr[1].w : xr[0].w;
        Ws[0][lcol + 0][lrow + 64 * h] = h ? wr[1].x : wr[0].x;
        Ws[0][lcol + 1][lrow + 64 * h] = h ? wr[1].y : wr[0].y;
        Ws[0][lcol + 2][lrow + 64 * h] = h ? wr[1].z : wr[0].z;
        Ws[0][lcol + 3][lrow + 64 * h] = h ? wr[1].w : wr[0].w;
    }
    __syncthreads();

    const int NK = H / BK;  // 128
    for (int kt = 0; kt < NK; kt++) {
        const int cur = kt & 1;
        if (kt + 1 < NK) {
            const float* xp = Xptr + (size_t)(kt + 1) * BK;
            const float* wp = Wptr + (size_t)(kt + 1) * BK;
            xr[0] = *reinterpret_cast<const float4*>(xp);
            xr[1] = *reinterpret_cast<const float4*>(xp + (size_t)64 * H);
            wr[0] = *reinterpret_cast<const float4*>(wp);
            wr[1] = *reinterpret_cast<const float4*>(wp + (size_t)64 * H);
        }

#pragma unroll
        for (int k = 0; k < BK; k++) {
            float a[TM], b[TN];
            // 32B-aligned vector loads (pad keeps 16B alignment: (BM+4)*4 = 528 % 16 == 0)
            float4 av0 = *reinterpret_cast<const float4*>(&Xs[cur][k][ty * TM]);
            float4 av1 = *reinterpret_cast<const float4*>(&Xs[cur][k][ty * TM + 4]);
            float4 bv0 = *reinterpret_cast<const float4*>(&Ws[cur][k][tx * TN]);
            float4 bv1 = *reinterpret_cast<const float4*>(&Ws[cur][k][tx * TN + 4]);
            a[0] = av0.x; a[1] = av0.y; a[2] = av0.z; a[3] = av0.w;
            a[4] = av1.x; a[5] = av1.y; a[6] = av1.z; a[7] = av1.w;
            b[0] = bv0.x; b[1] = bv0.y; b[2] = bv0.z; b[3] = bv0.w;
            b[4] = bv1.x; b[5] = bv1.y; b[6] = bv1.z; b[7] = bv1.w;
#pragma unroll
            for (int i = 0; i < TM; i++)
#pragma unroll
                for (int j = 0; j < TN; j++) acc[i][j] = fmaf(a[i], b[j], acc[i][j]);
        }

        if (kt + 1 < NK) {
            const int nxt = (kt + 1) & 1;
#pragma unroll
            for (int h = 0; h < 2; h++) {
                Xs[nxt][lcol + 0][lrow + 64 * h] = h ? xr[1].x : xr[0].x;
                Xs[nxt][lcol + 1][lrow + 64 * h] = h ? xr[1].y : xr[0].y;
                Xs[nxt][lcol + 2][lrow + 64 * h] = h ? xr[1].z : xr[0].z;
                Xs[nxt][lcol + 3][lrow + 64 * h] = h ? xr[1].w : xr[0].w;
                Ws[nxt][lcol + 0][lrow + 64 * h] = h ? wr[1].x : wr[0].x;
                Ws[nxt][lcol + 1][lrow + 64 * h] = h ? wr[1].y : wr[0].y;
                Ws[nxt][lcol + 2][lrow + 64 * h] = h ? wr[1].z : wr[0].z;
                Ws[nxt][lcol + 3][lrow + 64 * h] = h ? wr[1].w : wr[0].w;
            }
            __syncthreads();
        }
    }

    // write back: token m0 + ty*8 + i, expert tx*8 + j (E == BN, fully covered)
#pragma unroll
    for (int i = 0; i < TM; i++) {
        float* crow = C + (size_t)(m0 + ty * TM + i) * E + tx * TN;
        float4 v0 = make_float4(acc[i][0], acc[i][1], acc[i][2], acc[i][3]);
        float4 v1 = make_float4(acc[i][4], acc[i][5], acc[i][6], acc[i][7]);
        *reinterpret_cast<float4*>(crow) = v0;
        *reinterpret_cast<float4*>(crow + 4) = v1;
    }
}

// One warp per token: top-8 by iterative argmax (ties -> lower index, matching
// jax.lax.top_k), then normalized softmax weights. Full-softmax denominator
// cancels under NORM_TOPK_PROB, so only top-8 exps are needed.
__global__ __launch_bounds__(256) void topk_kernel(const float* __restrict__ C,
                                                   float* __restrict__ vals,
                                                   float* __restrict__ idxf) {
    const int token = (blockIdx.x * blockDim.x + threadIdx.x) >> 5;
    const int lane = threadIdx.x & 31;
    if (token >= T) return;

    const float* row = C + (size_t)token * E;
    float v[4];
    int id[4];
#pragma unroll
    for (int j = 0; j < 4; j++) {
        id[j] = lane + 32 * j;
        v[j] = row[id[j]];
    }

    float topv[TOPK];
    int topi[TOPK];
#pragma unroll
    for (int it = 0; it < TOPK; it++) {
        // local argmax (ids ascending -> strict '>' keeps lowest index on ties)
        float bv = v[0];
        int bi = id[0];
#pragma unroll
        for (int j = 1; j < 4; j++) {
            if (v[j] > bv) { bv = v[j]; bi = id[j]; }
        }
        // warp argmax, tie -> lower index
#pragma unroll
        for (int off = 16; off > 0; off >>= 1) {
            float ov = __shfl_xor_sync(0xFFFFFFFFu, bv, off);
            int oi = __shfl_xor_sync(0xFFFFFFFFu, bi, off);
            if (ov > bv || (ov == bv && oi < bi)) { bv = ov; bi = oi; }
        }
        topv[it] = bv;
        topi[it] = bi;
        // retire winner
#pragma unroll
        for (int j = 0; j < 4; j++)
            if (id[j] == bi) v[j] = -INFINITY;
    }

    // normalized weights: exp(l_i - m) / sum_top8 exp(l_j - m)
    const float m = topv[0];
    float e[TOPK];
    float s = 0.0f;
#pragma unroll
    for (int i = 0; i < TOPK; i++) {
        e[i] = expf(topv[i] - m);
        s += e[i];
    }
    const float inv = 1.0f / s;

    if (lane < TOPK) {
        vals[(size_t)token * TOPK + lane] = e[lane] * inv;
        idxf[(size_t)token * TOPK + lane] = (float)topi[lane];
    }
}

extern "C" void kernel_launch(void* const* d_in, const int* in_sizes, int n_in,
                              void* d_out, int out_size) {
    const float* X = (const float*)d_in[0];  // [T, H]
    const float* W = (const float*)d_in[1];  // [E, H]
    float* out = (float*)d_out;
    float* logits = out;                          // T*E
    float* vals = out + (size_t)T * E;            // T*TOPK
    float* idxf = vals + (size_t)T * TOPK;        // T*TOPK (indices as float)

    router_gemm<<<T / BM, 256>>>(X, W, logits);
    topk_kernel<<<T / 8, 256>>>(logits, vals, idxf);
}

// round 6
// speedup vs baseline: 1.8082x; 1.8082x over previous
#include <cuda_runtime.h>
#include <cuda_bf16.h>
#include <cstdint>
#include <math.h>

// ---------------- problem constants ----------------
constexpr int T = 16384;   // tokens
constexpr int H = 2048;    // hidden
constexpr int E = 128;     // experts
constexpr int TOPK = 8;

// ---------------- GEMM config ----------------
constexpr int BM = 128;               // tokens per CTA
constexpr int CHUNK = 32;             // fp32 k per pipeline chunk
constexpr int NCHUNK = H / CHUNK;     // 64
constexpr int TSTRIDE = 80;           // bytes per tile row: 64B data + 16B pad (conflict-free ldmatrix)
constexpr int TILE_B = 128 * TSTRIDE; // 10240 B per component tile
constexpr int STAGE_B = 6 * TILE_B;   // A1,A2,A3,B1,B2,B3 = 61440
constexpr int SMEM_TOTAL = 2 * STAGE_B;  // 122880

// pre-split W components (bf16 triple-split of fp32), [E][H]
__device__ __align__(16) __nv_bfloat16 g_w1[E * H];
__device__ __align__(16) __nv_bfloat16 g_w2[E * H];
__device__ __align__(16) __nv_bfloat16 g_w3[E * H];

// ---------------- helpers ----------------
__device__ __forceinline__ uint32_t smem_u32(const void* p) {
    uint32_t a;
    asm("{ .reg .u64 t; cvta.to.shared.u64 t, %1; cvt.u32.u64 %0, t; }" : "=r"(a) : "l"(p));
    return a;
}
__device__ __forceinline__ void ldsm4(uint32_t* r, uint32_t addr) {
    asm volatile("ldmatrix.sync.aligned.m8n8.x4.shared.b16 {%0,%1,%2,%3}, [%4];"
                 : "=r"(r[0]), "=r"(r[1]), "=r"(r[2]), "=r"(r[3]) : "r"(addr));
}
__device__ __forceinline__ void mma16816(float* c, const uint32_t* a, const uint32_t* b) {
    asm volatile(
        "mma.sync.aligned.m16n8k16.row.col.f32.bf16.bf16.f32 "
        "{%0,%1,%2,%3}, {%4,%5,%6,%7}, {%8,%9}, {%0,%1,%2,%3};"
        : "+f"(c[0]), "+f"(c[1]), "+f"(c[2]), "+f"(c[3])
        : "r"(a[0]), "r"(a[1]), "r"(a[2]), "r"(a[3]), "r"(b[0]), "r"(b[1]));
}

// ---------------- W triple-split precompute ----------------
__global__ __launch_bounds__(256) void split_w_kernel(const float* __restrict__ W) {
    int i = blockIdx.x * blockDim.x + threadIdx.x;   // one float4 per thread
    float4 v = reinterpret_cast<const float4*>(W)[i];
    __nv_bfloat162 a0 = __floats2bfloat162_rn(v.x, v.y);
    __nv_bfloat162 a1 = __floats2bfloat162_rn(v.z, v.w);
    float r0 = v.x - __low2float(a0), r1 = v.y - __high2float(a0);
    float r2 = v.z - __low2float(a1), r3 = v.w - __high2float(a1);
    __nv_bfloat162 b0 = __floats2bfloat162_rn(r0, r1);
    __nv_bfloat162 b1 = __floats2bfloat162_rn(r2, r3);
    r0 -= __low2float(b0); r1 -= __high2float(b0);
    r2 -= __low2float(b1); r3 -= __high2float(b1);
    __nv_bfloat162 c0 = __floats2bfloat162_rn(r0, r1);
    __nv_bfloat162 c1 = __floats2bfloat162_rn(r2, r3);
    reinterpret_cast<__nv_bfloat162*>(g_w1)[2 * i] = a0;
    reinterpret_cast<__nv_bfloat162*>(g_w1)[2 * i + 1] = a1;
    reinterpret_cast<__nv_bfloat162*>(g_w2)[2 * i] = b0;
    reinterpret_cast<__nv_bfloat162*>(g_w2)[2 * i + 1] = b1;
    reinterpret_cast<__nv_bfloat162*>(g_w3)[2 * i] = c0;
    reinterpret_cast<__nv_bfloat162*>(g_w3)[2 * i + 1] = c1;
}

// ---------------- bf16x6 HMMA router GEMM ----------------
// C[t][e] = X[t][:] . W[e][:], exactly fp32-equivalent via 3-way bf16 splits.
__global__ __launch_bounds__(256, 1) void router_gemm_mma(const float* __restrict__ X,
                                                          float* __restrict__ Cout) {
    extern __shared__ char smem[];
    const int tid = threadIdx.x;
    const int wid = tid >> 5;
    const int lane = tid & 31;
    const int m0 = blockIdx.x * BM;

    // gmem load mapping: 2 threads per row, 16 floats (64B) each
    const int lrow = tid >> 1;          // 0..127
    const int lhalf = tid & 1;          // 0/1
    const float* Xbase = X + (size_t)(m0 + lrow) * H + lhalf * 16;
    const __nv_bfloat16* Wb1 = g_w1 + (size_t)lrow * H + lhalf * 16;
    const __nv_bfloat16* Wb2 = g_w2 + (size_t)lrow * H + lhalf * 16;
    const __nv_bfloat16* Wb3 = g_w3 + (size_t)lrow * H + lhalf * 16;
    const uint32_t rb = (uint32_t)lrow * TSTRIDE + lhalf * 32;  // smem tile byte base

    // warp tile: 2 warps in M (64 rows), 4 warps in N (32 cols)
    const int wm = (wid >> 2) * 64;
    const int wn = (wid & 3) * 32;

    float acc[4][4][4];
#pragma unroll
    for (int mt = 0; mt < 4; mt++)
#pragma unroll
        for (int nt = 0; nt < 4; nt++)
#pragma unroll
            for (int j = 0; j < 4; j++) acc[mt][nt][j] = 0.0f;

    float4 xv[4];
    uint4 wv[3][2];

    // prefetch chunk 0
    {
        const float* xp = Xbase;
#pragma unroll
        for (int q = 0; q < 4; q++) xv[q] = *reinterpret_cast<const float4*>(xp + q * 4);
        wv[0][0] = *reinterpret_cast<const uint4*>(Wb1);
        wv[0][1] = *reinterpret_cast<const uint4*>(Wb1 + 8);
        wv[1][0] = *reinterpret_cast<const uint4*>(Wb2);
        wv[1][1] = *reinterpret_cast<const uint4*>(Wb2 + 8);
        wv[2][0] = *reinterpret_cast<const uint4*>(Wb3);
        wv[2][1] = *reinterpret_cast<const uint4*>(Wb3 + 8);
    }

    const uint32_t sbase = smem_u32(smem);

#pragma unroll 1
    for (int c = 0; c < NCHUNK; c++) {
        const int cur = c & 1;
        char* stage = smem + cur * STAGE_B;

        // ---- store phase: split X regs -> 3 bf16 A tiles; copy W regs -> B tiles ----
        {
            char* A1 = stage;
            char* A2 = stage + TILE_B;
            char* A3 = stage + 2 * TILE_B;
#pragma unroll
            for (int q = 0; q < 4; q++) {
                float4 v = xv[q];
                uint32_t off = rb + q * 8;
                __nv_bfloat162 p1a = __floats2bfloat162_rn(v.x, v.y);
                __nv_bfloat162 p1b = __floats2bfloat162_rn(v.z, v.w);
                *reinterpret_cast<uint2*>(A1 + off) =
                    make_uint2(*reinterpret_cast<uint32_t*>(&p1a), *reinterpret_cast<uint32_t*>(&p1b));
                float r0 = v.x - __low2float(p1a);
                float r1 = v.y - __high2float(p1a);
                float r2 = v.z - __low2float(p1b);
                float r3 = v.w - __high2float(p1b);
                __nv_bfloat162 p2a = __floats2bfloat162_rn(r0, r1);
                __nv_bfloat162 p2b = __floats2bfloat162_rn(r2, r3);
                *reinterpret_cast<uint2*>(A2 + off) =
                    make_uint2(*reinterpret_cast<uint32_t*>(&p2a), *reinterpret_cast<uint32_t*>(&p2b));
                r0 -= __low2float(p2a); r1 -= __high2float(p2a);
                r2 -= __low2float(p2b); r3 -= __high2float(p2b);
                __nv_bfloat162 p3a = __floats2bfloat162_rn(r0, r1);
                __nv_bfloat162 p3b = __floats2bfloat162_rn(r2, r3);
                *reinterpret_cast<uint2*>(A3 + off) =
                    make_uint2(*reinterpret_cast<uint32_t*>(&p3a), *reinterpret_cast<uint32_t*>(&p3b));
            }
#pragma unroll
            for (int comp = 0; comp < 3; comp++) {
                char* Bt = stage + (3 + comp) * TILE_B;
                *reinterpret_cast<uint4*>(Bt + rb) = wv[comp][0];
                *reinterpret_cast<uint4*>(Bt + rb + 16) = wv[comp][1];
            }
        }
        __syncthreads();

        // ---- prefetch chunk c+1 into regs (overlaps with MMA below) ----
        if (c + 1 < NCHUNK) {
            const float* xp = Xbase + (c + 1) * CHUNK;
#pragma unroll
            for (int q = 0; q < 4; q++) xv[q] = *reinterpret_cast<const float4*>(xp + q * 4);
            const int wo = (c + 1) * CHUNK;
            wv[0][0] = *reinterpret_cast<const uint4*>(Wb1 + wo);
            wv[0][1] = *reinterpret_cast<const uint4*>(Wb1 + wo + 8);
            wv[1][0] = *reinterpret_cast<const uint4*>(Wb2 + wo);
            wv[1][1] = *reinterpret_cast<const uint4*>(Wb2 + wo + 8);
            wv[2][0] = *reinterpret_cast<const uint4*>(Wb3 + wo);
            wv[2][1] = *reinterpret_cast<const uint4*>(Wb3 + wo + 8);
        }

        // ---- compute on stage cur ----
        const uint32_t st = sbase + cur * STAGE_B;
#pragma unroll
        for (int ks = 0; ks < 2; ks++) {
            // B fragments: 3 comps x 4 n-tiles (2 ldmatrix.x4 per comp)
            uint32_t bq[3][8];
            {
                const uint32_t nrow = wn + (lane & 7) + ((lane >> 4) & 1) * 8;
                const uint32_t koff = ks * 32 + ((lane >> 3) & 1) * 16;
#pragma unroll
                for (int comp = 0; comp < 3; comp++) {
                    uint32_t basea = st + (3 + comp) * TILE_B + nrow * TSTRIDE + koff;
                    ldsm4(&bq[comp][0], basea);                  // n-tiles 0,1
                    ldsm4(&bq[comp][4], basea + 16 * TSTRIDE);   // n-tiles 2,3
                }
            }
            // A comps on demand; terms (ca,cb) with ca+cb <= 2
            const uint32_t arow = wm + (lane & 15);
            const uint32_t akoff = ks * 32 + (lane >> 4) * 16;
#pragma unroll
            for (int ca = 0; ca < 3; ca++) {
                uint32_t abase = st + ca * TILE_B + arow * TSTRIDE + akoff;
                uint32_t aq[4][4];
#pragma unroll
                for (int mt = 0; mt < 4; mt++) ldsm4(aq[mt], abase + mt * 16 * TSTRIDE);
#pragma unroll
                for (int cb = 0; cb < 3; cb++) {
                    if (ca + cb > 2) continue;
#pragma unroll
                    for (int mt = 0; mt < 4; mt++)
#pragma unroll
                        for (int nt = 0; nt < 4; nt++)
                            mma16816(acc[mt][nt], aq[mt], &bq[cb][nt * 2]);
                }
            }
        }
    }

    // ---- epilogue ----
    const int trow = lane >> 2;
    const int tcol = (lane & 3) * 2;
#pragma unroll
    for (int mt = 0; mt < 4; mt++) {
#pragma unroll
        for (int nt = 0; nt < 4; nt++) {
            const int row = m0 + wm + mt * 16 + trow;
            const int col = wn + nt * 8 + tcol;
            *reinterpret_cast<float2*>(Cout + (size_t)row * E + col) =
                make_float2(acc[mt][nt][0], acc[mt][nt][1]);
            *reinterpret_cast<float2*>(Cout + (size_t)(row + 8) * E + col) =
                make_float2(acc[mt][nt][2], acc[mt][nt][3]);
        }
    }
}

// ---------------- top-k (unchanged, proven correct) ----------------
__global__ __launch_bounds__(256) void topk_kernel(const float* __restrict__ C,
                                                   float* __restrict__ vals,
                                                   float* __restrict__ idxf) {
    const int token = (blockIdx.x * blockDim.x + threadIdx.x) >> 5;
    const int lane = threadIdx.x & 31;
    if (token >= T) return;

    const float* rowp = C + (size_t)token * E;
    float v[4];
    int id[4];
#pragma unroll
    for (int j = 0; j < 4; j++) {
        id[j] = lane + 32 * j;
        v[j] = rowp[id[j]];
    }

    float topv[TOPK];
    int topi[TOPK];
#pragma unroll
    for (int it = 0; it < TOPK; it++) {
        float bv = v[0];
        int bi = id[0];
#pragma unroll
        for (int j = 1; j < 4; j++)
            if (v[j] > bv) { bv = v[j]; bi = id[j]; }
#pragma unroll
        for (int off = 16; off > 0; off >>= 1) {
            float ov = __shfl_xor_sync(0xFFFFFFFFu, bv, off);
            int oi = __shfl_xor_sync(0xFFFFFFFFu, bi, off);
            if (ov > bv || (ov == bv && oi < bi)) { bv = ov; bi = oi; }
        }
        topv[it] = bv;
        topi[it] = bi;
#pragma unroll
        for (int j = 0; j < 4; j++)
            if (id[j] == bi) v[j] = -INFINITY;
    }

    const float m = topv[0];
    float e[TOPK];
    float s = 0.0f;
#pragma unroll
    for (int i = 0; i < TOPK; i++) {
        e[i] = expf(topv[i] - m);
        s += e[i];
    }
    const float inv = 1.0f / s;

    if (lane < TOPK) {
        vals[(size_t)token * TOPK + lane] = e[lane] * inv;
        idxf[(size_t)token * TOPK + lane] = (float)topi[lane];
    }
}

extern "C" void kernel_launch(void* const* d_in, const int* in_sizes, int n_in,
                              void* d_out, int out_size) {
    const float* X = (const float*)d_in[0];  // [T, H]
    const float* W = (const float*)d_in[1];  // [E, H]
    float* out = (float*)d_out;
    float* logits = out;                      // T*E
    float* vals = out + (size_t)T * E;        // T*TOPK
    float* idxf = vals + (size_t)T * TOPK;    // T*TOPK

    cudaFuncSetAttribute(router_gemm_mma, cudaFuncAttributeMaxDynamicSharedMemorySize, SMEM_TOTAL);

    split_w_kernel<<<(E * H / 4) / 256, 256>>>(W);
    router_gemm_mma<<<T / BM, 256, SMEM_TOTAL>>>(X, logits);
    topk_kernel<<<T / 8, 256>>>(logits, vals, idxf);
}